// round 1
// baseline (speedup 1.0000x reference)
#include <cuda_runtime.h>
#include <cstdint>

#define B_ 32
#define C_ 256
#define D_ 1024
#define Q_ 128

// ---------------- scratch (static device globals: allocation-free) ----------
__device__ float g_sim[B_ * Q_ * D_];   // 16 MB
__device__ float g_s1 [B_ * Q_ * D_];   // 16 MB  softmax over q
__device__ float g_s2 [B_ * Q_ * D_];   // 16 MB  softmax over d
__device__ float g_dotD[B_ * D_];
__device__ float g_dotQ[B_ * Q_];

enum { M_SIM = 0, M_DD2Q, M_QQ2D, M_DQ2D, M_QD2Q };

// ---------------- dot products: dotD[b,d] = w_d . doc[:,d], dotQ analog -----
__global__ void dots_kernel(const float* __restrict__ doc,
                            const float* __restrict__ query,
                            const float* __restrict__ W) {
    int idx = blockIdx.x * 256 + threadIdx.x;
    if (idx < B_ * D_) {
        int b = idx / D_, d = idx % D_;
        const float* p = doc + (size_t)b * C_ * D_ + d;
        float s = 0.f;
#pragma unroll 8
        for (int c = 0; c < C_; c++) s = fmaf(W[c], p[(size_t)c * D_], s);
        g_dotD[idx] = s;
    } else {
        int r = idx - B_ * D_;
        if (r < B_ * Q_) {
            int b = r / Q_, q = r % Q_;
            const float* p = query + (size_t)b * C_ * Q_ + q;
            float s = 0.f;
#pragma unroll 8
            for (int c = 0; c < C_; c++) s = fmaf(W[C_ + c], p[c * Q_], s);
            g_dotQ[r] = s;
        }
    }
}

// ---------------- softmax over q (columns of sim), 3-pass, L2-resident ------
__global__ void softmax_q_kernel() {
    int b = blockIdx.y;
    int d = blockIdx.x * 256 + threadIdx.x;
    const float* p = g_sim + (size_t)b * Q_ * D_ + d;
    float m = -1e30f;
#pragma unroll 4
    for (int q = 0; q < Q_; q++) m = fmaxf(m, p[q * D_]);
    float s = 0.f;
#pragma unroll 4
    for (int q = 0; q < Q_; q++) s += __expf(p[q * D_] - m);
    float inv = 1.f / s;
    float* o = g_s1 + (size_t)b * Q_ * D_ + d;
#pragma unroll 4
    for (int q = 0; q < Q_; q++) o[q * D_] = __expf(p[q * D_] - m) * inv;
}

// ---------------- softmax over d (rows of sim) ------------------------------
__global__ void softmax_d_kernel() {
    int b = blockIdx.y, q = blockIdx.x;
    const float* p = g_sim + (size_t)(b * Q_ + q) * D_;
    float* o = g_s2 + (size_t)(b * Q_ + q) * D_;
    int t = threadIdx.x;
    float x[4];
    float m = -1e30f;
#pragma unroll
    for (int i = 0; i < 4; i++) { x[i] = p[t + 256 * i]; m = fmaxf(m, x[i]); }
#pragma unroll
    for (int off = 16; off; off >>= 1) m = fmaxf(m, __shfl_xor_sync(0xffffffffu, m, off));
    __shared__ float red[8];
    if ((t & 31) == 0) red[t >> 5] = m;
    __syncthreads();
    m = red[0];
#pragma unroll
    for (int i = 1; i < 8; i++) m = fmaxf(m, red[i]);
    float e[4];
    float s = 0.f;
#pragma unroll
    for (int i = 0; i < 4; i++) { e[i] = __expf(x[i] - m); s += e[i]; }
#pragma unroll
    for (int off = 16; off; off >>= 1) s += __shfl_xor_sync(0xffffffffu, s, off);
    __syncthreads();
    if ((t & 31) == 0) red[t >> 5] = s;
    __syncthreads();
    s = 0.f;
#pragma unroll
    for (int i = 0; i < 8; i++) s += red[i];
    float inv = 1.f / s;
#pragma unroll
    for (int i = 0; i < 4; i++) o[t + 256 * i] = e[i] * inv;
}

// ---------------- templated tiled GEMM, fused per-mode epilogues ------------
// MT x NT tile, 256 threads, (MT/16)x(NT/16) microtile per thread, KT=16.
template <int MODE, int MT, int NT>
__global__ void __launch_bounds__(256) gemm_k(
    const float* __restrict__ doc, const float* __restrict__ query,
    const float* __restrict__ W,
    float* __restrict__ out_d, float* __restrict__ out_q) {
    constexpr int KT = 16;
    constexpr int TM = MT / 16, TN = NT / 16;
    const int b  = blockIdx.z;
    const int m0 = blockIdx.y * MT;
    const int n0 = blockIdx.x * NT;
    const int tid = threadIdx.x;
    const int tx = tid & 15, ty = tid >> 4;

    __shared__ float As[KT][MT + 4];
    __shared__ float Bs[KT][NT + 4];

    const float* Aptr = nullptr;
    const float* Bptr = nullptr;
    int K = 0, lda = 0;
    if constexpr (MODE == M_SIM) {
        K = C_; Bptr = doc + (size_t)b * C_ * D_;
    } else if constexpr (MODE == M_DD2Q) {
        K = Q_; Aptr = query + (size_t)b * C_ * Q_; lda = Q_;
        Bptr = g_s1 + (size_t)b * Q_ * D_;
    } else if constexpr (MODE == M_QQ2D) {
        K = D_; Aptr = doc + (size_t)b * C_ * D_; lda = D_;
        Bptr = g_s2 + (size_t)b * Q_ * D_;      // transposed access
    } else if constexpr (MODE == M_DQ2D) {
        K = Q_; Aptr = out_q + (size_t)b * 4 * C_ * Q_ + C_ * Q_; lda = Q_;
        Bptr = g_s1 + (size_t)b * Q_ * D_;
    } else {                                     // M_QD2Q
        K = D_; Aptr = out_d + (size_t)b * 4 * C_ * D_ + C_ * D_; lda = D_;
        Bptr = g_s2 + (size_t)b * Q_ * D_;      // transposed access
    }

    float acc[TM][TN];
#pragma unroll
    for (int i = 0; i < TM; i++)
#pragma unroll
        for (int j = 0; j < TN; j++) acc[i][j] = 0.f;

    for (int k0 = 0; k0 < K; k0 += KT) {
        // ---- load A tile into As[k][m] ----
        if constexpr (MODE == M_SIM) {
            // A[m=q, k=c] = w_s[c] * query[b, c, q]  (col-major along m, coalesced)
#pragma unroll
            for (int i = 0; i < MT * KT / 256; i++) {
                int lin = tid + i * 256;
                int m = lin % MT, k = lin / MT;
                As[k][m] = W[2 * C_ + k0 + k] *
                           query[(size_t)b * C_ * Q_ + (size_t)(k0 + k) * Q_ + (m0 + m)];
            }
        } else {
            // row-major A (m,k)
#pragma unroll
            for (int i = 0; i < MT * KT / 256; i++) {
                int lin = tid + i * 256;
                int k = lin & (KT - 1), m = lin / KT;
                As[k][m] = Aptr[(size_t)(m0 + m) * lda + (k0 + k)];
            }
        }
        // ---- load B tile into Bs[k][n] ----
        if constexpr (MODE == M_QQ2D || MODE == M_QD2Q) {
            // B[k=d, n=q] = s2[b, q, d]  (transposed: coalesced along k)
#pragma unroll
            for (int i = 0; i < NT * KT / 256; i++) {
                int lin = tid + i * 256;
                int k = lin & (KT - 1), n = lin / KT;
                Bs[k][n] = Bptr[(size_t)(n0 + n) * D_ + (k0 + k)];
            }
        } else {
            // row-major B (k,n), ld = D_
#pragma unroll
            for (int i = 0; i < NT * KT / 256; i++) {
                int lin = tid + i * 256;
                int n = lin % NT, k = lin / NT;
                Bs[k][n] = Bptr[(size_t)(k0 + k) * D_ + (n0 + n)];
            }
        }
        __syncthreads();

#pragma unroll
        for (int kk = 0; kk < KT; kk++) {
            float a[TM], bb[TN];
#pragma unroll
            for (int i = 0; i < TM; i++) a[i] = As[kk][ty * TM + i];
#pragma unroll
            for (int j = 0; j < TN; j++) bb[j] = Bs[kk][tx * TN + j];
#pragma unroll
            for (int i = 0; i < TM; i++)
#pragma unroll
                for (int j = 0; j < TN; j++)
                    acc[i][j] = fmaf(a[i], bb[j], acc[i][j]);
        }
        __syncthreads();
    }

    // ---- fused epilogues ----
#pragma unroll
    for (int i = 0; i < TM; i++) {
        int m = m0 + ty * TM + i;
#pragma unroll
        for (int j = 0; j < TN; j++) {
            int n = n0 + tx * TN + j;
            float v = acc[i][j];
            if constexpr (MODE == M_SIM) {
                g_sim[(size_t)b * Q_ * D_ + (size_t)m * D_ + n] =
                    v + g_dotQ[b * Q_ + m] + g_dotD[b * D_ + n];
            } else if constexpr (MODE == M_DD2Q) {
                size_t ob = (size_t)b * 4 * C_ * D_;
                float dv = doc[(size_t)b * C_ * D_ + (size_t)m * D_ + n];
                out_d[ob + (size_t)m * D_ + n] = dv;                     // doc copy
                out_d[ob + (size_t)(C_ + m) * D_ + n] = v;               // d_d2q
                out_d[ob + (size_t)(2 * C_ + m) * D_ + n] = dv * v;      // doc*d_d2q
            } else if constexpr (MODE == M_QQ2D) {
                size_t ob = (size_t)b * 4 * C_ * Q_;
                float qv = query[(size_t)b * C_ * Q_ + (size_t)m * Q_ + n];
                out_q[ob + (size_t)m * Q_ + n] = qv;                     // query copy
                out_q[ob + (size_t)(C_ + m) * Q_ + n] = v;               // q_q2d
                out_q[ob + (size_t)(2 * C_ + m) * Q_ + n] = qv * v;      // query*q_q2d
            } else if constexpr (MODE == M_DQ2D) {
                float dv = doc[(size_t)b * C_ * D_ + (size_t)m * D_ + n];
                out_d[(size_t)b * 4 * C_ * D_ + (size_t)(3 * C_ + m) * D_ + n] = dv * v;
            } else {                                                      // M_QD2Q
                float qv = query[(size_t)b * C_ * Q_ + (size_t)m * Q_ + n];
                out_q[(size_t)b * 4 * C_ * Q_ + (size_t)(3 * C_ + m) * Q_ + n] = qv * v;
            }
        }
    }
}

// ---------------- launcher ---------------------------------------------------
extern "C" void kernel_launch(void* const* d_in, const int* in_sizes, int n_in,
                              void* d_out, int out_size) {
    const float* doc   = (const float*)d_in[0];
    const float* query = (const float*)d_in[1];
    const float* W     = (const float*)d_in[2];
    float* out_d = (float*)d_out;
    float* out_q = out_d + (size_t)B_ * 4 * C_ * D_;

    // 1) bias dot products
    dots_kernel<<<(B_ * D_ + B_ * Q_ + 255) / 256, 256>>>(doc, query, W);

    // 2) sim = cross-GEMM + biases
    gemm_k<M_SIM, 128, 128><<<dim3(D_ / 128, Q_ / 128, B_), 256>>>(doc, query, W, out_d, out_q);

    // 3) softmaxes
    softmax_q_kernel<<<dim3(D_ / 256, B_), 256>>>();
    softmax_d_kernel<<<dim3(Q_, B_), 256>>>();

    // 4) first-round GEMMs (epilogues write doc/query copies + products)
    gemm_k<M_DD2Q, 128, 128><<<dim3(D_ / 128, C_ / 128, B_), 256>>>(doc, query, W, out_d, out_q);
    gemm_k<M_QQ2D, 64, 128><<<dim3(Q_ / 128, C_ / 64, B_), 256>>>(doc, query, W, out_d, out_q);

    // 5) second-round GEMMs (A operands read back from the output buffer)
    gemm_k<M_DQ2D, 128, 128><<<dim3(D_ / 128, C_ / 128, B_), 256>>>(doc, query, W, out_d, out_q);
    gemm_k<M_QD2Q, 64, 128><<<dim3(Q_ / 128, C_ / 64, B_), 256>>>(doc, query, W, out_d, out_q);
}

// round 6
// speedup vs baseline: 2.1260x; 2.1260x over previous
#include <cuda_runtime.h>
#include <cuda_bf16.h>
#include <cstdint>

#define B_ 32
#define C_ 256
#define D_ 1024
#define Q_ 128

// ---------------- scratch ----------------------------------------------------
__device__ float    g_sim[B_ * Q_ * D_];   // fp32 sim
__device__ uint32_t g_s1p[B_ * Q_ * D_];   // softmax over q, packed (hi bf16 | lo bf16<<16)
__device__ uint32_t g_s2p[B_ * Q_ * D_];   // softmax over d, packed
__device__ float    g_dotD[B_ * D_];
__device__ float    g_dotQ[B_ * Q_];

// ---------------- helpers -----------------------------------------------------
__device__ __forceinline__ uint32_t smem_u32(const void* p) {
    uint32_t a;
    asm("{ .reg .u64 t; cvta.to.shared.u64 t, %1; cvt.u32.u64 %0, t; }" : "=r"(a) : "l"(p));
    return a;
}
__device__ __forceinline__ void ldm_x4(uint32_t& r0, uint32_t& r1, uint32_t& r2, uint32_t& r3,
                                       uint32_t addr) {
    asm volatile("ldmatrix.sync.aligned.m8n8.x4.shared.b16 {%0,%1,%2,%3}, [%4];"
                 : "=r"(r0), "=r"(r1), "=r"(r2), "=r"(r3) : "r"(addr));
}
__device__ __forceinline__ void mma_bf16(float* d, const uint32_t* a, uint32_t b0, uint32_t b1) {
    asm volatile(
        "mma.sync.aligned.m16n8k16.row.col.f32.bf16.bf16.f32 "
        "{%0,%1,%2,%3}, {%4,%5,%6,%7}, {%8,%9}, {%0,%1,%2,%3};"
        : "+f"(d[0]), "+f"(d[1]), "+f"(d[2]), "+f"(d[3])
        : "r"(a[0]), "r"(a[1]), "r"(a[2]), "r"(a[3]), "r"(b0), "r"(b1));
}

// ---------------- bf16 split helpers -----------------------------------------
__device__ __forceinline__ uint32_t bfpack(__nv_bfloat16 a, __nv_bfloat16 b) {
    return (uint32_t)__bfloat16_as_ushort(a) | ((uint32_t)__bfloat16_as_ushort(b) << 16);
}
__device__ __forceinline__ void split4(float x0, float x1, float x2, float x3,
                                       uint32_t& h0, uint32_t& h1,
                                       uint32_t& l0, uint32_t& l1) {
    __nv_bfloat16 a0 = __float2bfloat16(x0), a1 = __float2bfloat16(x1);
    __nv_bfloat16 a2 = __float2bfloat16(x2), a3 = __float2bfloat16(x3);
    __nv_bfloat16 b0 = __float2bfloat16(x0 - __bfloat162float(a0));
    __nv_bfloat16 b1 = __float2bfloat16(x1 - __bfloat162float(a1));
    __nv_bfloat16 b2 = __float2bfloat16(x2 - __bfloat162float(a2));
    __nv_bfloat16 b3 = __float2bfloat16(x3 - __bfloat162float(a3));
    h0 = bfpack(a0, a1); h1 = bfpack(a2, a3);
    l0 = bfpack(b0, b1); l1 = bfpack(b2, b3);
}
// 8-byte store of 4 bf16 (k multiple of 4) into an 80B-stride row-major tile
__device__ __forceinline__ void sts8(uint32_t base, int row, int k, uint32_t w0, uint32_t w1) {
    uint32_t off = (uint32_t)(row * 80 + k * 2);
    asm volatile("st.shared.v2.b32 [%0], {%1, %2};" :: "r"(base + off), "r"(w0), "r"(w1) : "memory");
}

// ---------------- dots: dotD[b,d] = w_d . doc, dotQ[b,q] = w_q . query -------
__global__ void dots_kernel(const float* __restrict__ doc,
                            const float* __restrict__ query,
                            const float* __restrict__ W) {
    int idx = blockIdx.x * 256 + threadIdx.x;
    if (idx < B_ * D_) {
        int b = idx / D_, d = idx % D_;
        const float* p = doc + (size_t)b * C_ * D_ + d;
        float s = 0.f;
#pragma unroll 8
        for (int c = 0; c < C_; c++) s = fmaf(W[c], p[(size_t)c * D_], s);
        g_dotD[idx] = s;
    } else {
        int r = idx - B_ * D_;
        if (r < B_ * Q_) {
            int b = r / Q_, q = r % Q_;
            const float* p = query + (size_t)b * C_ * Q_ + q;
            float s = 0.f;
#pragma unroll 8
            for (int c = 0; c < C_; c++) s = fmaf(W[C_ + c], p[c * Q_], s);
            g_dotQ[r] = s;
        }
    }
}

// ---------------- softmax over q -> packed bf16x2 ----------------------------
__global__ void softmax_q_kernel() {
    int b = blockIdx.y;
    int d = blockIdx.x * 256 + threadIdx.x;
    const float* p = g_sim + (size_t)b * Q_ * D_ + d;
    float m = -1e30f;
#pragma unroll 8
    for (int q = 0; q < Q_; q++) m = fmaxf(m, p[q * D_]);
    float s = 0.f;
#pragma unroll 8
    for (int q = 0; q < Q_; q++) s += __expf(p[q * D_] - m);
    float inv = 1.f / s;
    uint32_t* o = g_s1p + (size_t)b * Q_ * D_ + d;
#pragma unroll 8
    for (int q = 0; q < Q_; q++) {
        float v = __expf(p[q * D_] - m) * inv;
        __nv_bfloat16 h = __float2bfloat16(v);
        __nv_bfloat16 l = __float2bfloat16(v - __bfloat162float(h));
        o[q * D_] = bfpack(h, l);
    }
}

// ---------------- softmax over d -> packed bf16x2 ----------------------------
__global__ void softmax_d_kernel() {
    int b = blockIdx.y, q = blockIdx.x;
    const float* p = g_sim + (size_t)(b * Q_ + q) * D_;
    uint32_t* o = g_s2p + (size_t)(b * Q_ + q) * D_;
    int t = threadIdx.x;
    float x[4];
    float m = -1e30f;
#pragma unroll
    for (int i = 0; i < 4; i++) { x[i] = p[t + 256 * i]; m = fmaxf(m, x[i]); }
#pragma unroll
    for (int off = 16; off; off >>= 1) m = fmaxf(m, __shfl_xor_sync(0xffffffffu, m, off));
    __shared__ float red[8];
    if ((t & 31) == 0) red[t >> 5] = m;
    __syncthreads();
    m = red[0];
#pragma unroll
    for (int i = 1; i < 8; i++) m = fmaxf(m, red[i]);
    float e[4];
    float s = 0.f;
#pragma unroll
    for (int i = 0; i < 4; i++) { e[i] = __expf(x[i] - m); s += e[i]; }
#pragma unroll
    for (int off = 16; off; off >>= 1) s += __shfl_xor_sync(0xffffffffu, s, off);
    __syncthreads();
    if ((t & 31) == 0) red[t >> 5] = s;
    __syncthreads();
    s = 0.f;
#pragma unroll
    for (int i = 0; i < 8; i++) s += red[i];
    float inv = 1.f / s;
#pragma unroll
    for (int i = 0; i < 4; i++) {
        float v = e[i] * inv;
        __nv_bfloat16 h = __float2bfloat16(v);
        __nv_bfloat16 l = __float2bfloat16(v - __bfloat162float(h));
        o[t + 256 * i] = bfpack(h, l);
    }
}

// ---------------- warp-MMA GEMM, bf16x2 split, fused epilogues ---------------
enum { M_SIM = 0, M_DD2Q, M_QQ2D, M_DQ2D, M_QD2Q };

// 64 x 128 CTA tile, 256 threads (8 warps, 32x32 warp tiles), K chunks of 32.
// Static smem only (<=48KB), no host attribute calls needed.
template <int MODE, int KTOT>
__global__ void __launch_bounds__(256, 1)
mma_gemm(const float* __restrict__ doc, const float* __restrict__ query,
         const float* __restrict__ W,
         float* __restrict__ out_d, float* __restrict__ out_q) {
    constexpr int MT = 64;
    constexpr int NT8 = 4;    // 32-wide warp tile = 4 n8 tiles
    constexpr int NG16 = 2;   // 2 x 16-wide ldmatrix groups

    __shared__ __align__(16) char smem[33280];  // staging 30720 | Ct 33280 (union)
    const uint32_t sbase = smem_u32(smem);
    const int tid = threadIdx.x, wid = tid >> 5, lid = tid & 31;
    const int b = blockIdx.z, m0 = blockIdx.y * MT, n0 = blockIdx.x * 128;

    // staging: A hi/lo (64 x 32 bf16, 80B stride), B hi/lo (128 x 32)
    const uint32_t aH = sbase;
    const uint32_t aL = aH + 64 * 80;
    const uint32_t bH = aL + 64 * 80;
    const uint32_t bL = bH + 128 * 80;

    const int mw = (wid & 1) * 32;
    const int nw = (wid >> 1) * 32;

    // A source (K-major natural for all but SIM)
    const float* Ap = nullptr; int lda = 0;
    if constexpr (MODE == M_DD2Q) { Ap = query + (size_t)b * C_ * Q_; lda = Q_; }
    else if constexpr (MODE == M_QQ2D) { Ap = doc + (size_t)b * C_ * D_; lda = D_; }
    else if constexpr (MODE == M_DQ2D) { Ap = out_q + (size_t)b * 4 * C_ * Q_ + C_ * Q_; lda = Q_; }
    else if constexpr (MODE == M_QD2Q) { Ap = out_d + (size_t)b * 4 * C_ * D_ + (size_t)C_ * D_; lda = D_; }

    const uint32_t* Bp = nullptr;   // packed softmax source
    if constexpr (MODE == M_DD2Q || MODE == M_DQ2D) Bp = g_s1p + (size_t)b * Q_ * D_;
    if constexpr (MODE == M_QQ2D || MODE == M_QD2Q) Bp = g_s2p + (size_t)b * Q_ * D_;

    float acc[2][NT8][4];
#pragma unroll
    for (int i = 0; i < 2; i++)
#pragma unroll
        for (int j = 0; j < NT8; j++)
#pragma unroll
            for (int r = 0; r < 4; r++) acc[i][j][r] = 0.f;

    // per-lane ldmatrix offset: row (l&15)*80, col-8 group (l>>4)*16B
    const uint32_t lmOff = (uint32_t)((lid & 15) * 80 + (lid >> 4) * 16);

    constexpr int NCH = KTOT / 32;
    for (int ch = 0; ch < NCH; ch++) {
        const int k0 = ch * 32;

        // ---- stage A (64 rows x 32 k, hi+lo) ----
        if constexpr (MODE == M_SIM) {
#pragma unroll
            for (int i = 0; i < 2; i++) {
                int lin = tid + i * 256;
                int q = m0 + (lin & 63), cg = lin >> 6;      // cg 0..7
                int c = k0 + cg * 4;
                const float* qp = query + (size_t)b * C_ * Q_ + (size_t)c * Q_ + q;
                float x0 = W[2 * C_ + c + 0] * qp[0 * Q_];
                float x1 = W[2 * C_ + c + 1] * qp[1 * Q_];
                float x2 = W[2 * C_ + c + 2] * qp[2 * Q_];
                float x3 = W[2 * C_ + c + 3] * qp[3 * Q_];
                uint32_t h0, h1, l0, l1; split4(x0, x1, x2, x3, h0, h1, l0, l1);
                sts8(aH, lin & 63, cg * 4, h0, h1);
                sts8(aL, lin & 63, cg * 4, l0, l1);
            }
        } else {
#pragma unroll
            for (int i = 0; i < 2; i++) {
                int lin = tid + i * 256;
                int r = lin >> 3, g = lin & 7;
                float4 v = *(const float4*)(Ap + (size_t)(m0 + r) * lda + k0 + g * 4);
                uint32_t h0, h1, l0, l1; split4(v.x, v.y, v.z, v.w, h0, h1, l0, l1);
                sts8(aH, r, g * 4, h0, h1);
                sts8(aL, r, g * 4, l0, l1);
            }
        }
        // ---- stage B (128 rows x 32 k, hi+lo) ----
        if constexpr (MODE == M_SIM) {
#pragma unroll
            for (int i = 0; i < 4; i++) {
                int lin = tid + i * 256;
                int dn = lin & 127, cg = lin >> 7;           // cg 0..7
                int c = k0 + cg * 4;
                const float* dp = doc + (size_t)b * C_ * D_ + (size_t)c * D_ + (n0 + dn);
                float x0 = dp[0];
                float x1 = dp[(size_t)D_];
                float x2 = dp[2 * (size_t)D_];
                float x3 = dp[3 * (size_t)D_];
                uint32_t h0, h1, l0, l1; split4(x0, x1, x2, x3, h0, h1, l0, l1);
                sts8(bH, dn, cg * 4, h0, h1);
                sts8(bL, dn, cg * 4, l0, l1);
            }
        } else if constexpr (MODE == M_DD2Q || MODE == M_DQ2D) {
            // B[n=d][k=q] from s1p[q][d] (transpose read, packed bf16x2)
#pragma unroll
            for (int i = 0; i < 4; i++) {
                int lin = tid + i * 256;
                int dn = lin & 127, qg = lin >> 7;           // qg 0..7
                int q = k0 + qg * 4;
                const uint32_t* sp = Bp + (size_t)q * D_ + (n0 + dn);
                uint32_t p0 = sp[0], p1 = sp[D_], p2 = sp[2 * D_], p3 = sp[3 * D_];
                uint32_t h0 = (p0 & 0xFFFFu) | (p1 << 16), h1 = (p2 & 0xFFFFu) | (p3 << 16);
                uint32_t l0 = (p0 >> 16) | (p1 & 0xFFFF0000u), l1 = (p2 >> 16) | (p3 & 0xFFFF0000u);
                sts8(bH, dn, qg * 4, h0, h1);
                sts8(bL, dn, qg * 4, l0, l1);
            }
        } else {
            // B[n=q][k=d] from s2p[q][d] (natural K-major, packed bf16x2)
#pragma unroll
            for (int i = 0; i < 4; i++) {
                int lin = tid + i * 256;
                int r = lin >> 3, g = lin & 7;
                uint4 pv = *(const uint4*)(Bp + (size_t)r * D_ + k0 + g * 4);
                uint32_t h0 = (pv.x & 0xFFFFu) | (pv.y << 16), h1 = (pv.z & 0xFFFFu) | (pv.w << 16);
                uint32_t l0 = (pv.x >> 16) | (pv.y & 0xFFFF0000u), l1 = (pv.z >> 16) | (pv.w & 0xFFFF0000u);
                sts8(bH, r, g * 4, h0, h1);
                sts8(bL, r, g * 4, l0, l1);
            }
        }
        __syncthreads();

        // ---- compute: 2 k16 steps ----
#pragma unroll
        for (int kk = 0; kk < 32; kk += 16) {
            uint32_t aHf[2][4], aLf[2][4];
#pragma unroll
            for (int mt = 0; mt < 2; mt++) {
                uint32_t ao = (uint32_t)((mw + 16 * mt) * 80 + kk * 2) + lmOff;
                ldm_x4(aHf[mt][0], aHf[mt][1], aHf[mt][2], aHf[mt][3], aH + ao);
                ldm_x4(aLf[mt][0], aLf[mt][1], aLf[mt][2], aLf[mt][3], aL + ao);
            }
            uint32_t bHf[NG16][4], bLf[NG16][4];
#pragma unroll
            for (int ng = 0; ng < NG16; ng++) {
                uint32_t bo = (uint32_t)((nw + 16 * ng) * 80 + kk * 2) + lmOff;
                ldm_x4(bHf[ng][0], bHf[ng][1], bHf[ng][2], bHf[ng][3], bH + bo);
                ldm_x4(bLf[ng][0], bLf[ng][1], bLf[ng][2], bLf[ng][3], bL + bo);
            }
#pragma unroll
            for (int mt = 0; mt < 2; mt++)
#pragma unroll
                for (int nt = 0; nt < NT8; nt++) {
                    int ng = nt >> 1, half = nt & 1;   // x4: {r0,r2}=n0-7, {r1,r3}=n8-15
                    uint32_t b0h = bHf[ng][half], b1h = bHf[ng][2 + half];
                    uint32_t b0l = bLf[ng][half], b1l = bLf[ng][2 + half];
                    mma_bf16(acc[mt][nt], aHf[mt], b0h, b1h);
                    mma_bf16(acc[mt][nt], aHf[mt], b0l, b1l);
                    mma_bf16(acc[mt][nt], aLf[mt], b0h, b1h);
                }
        }
        __syncthreads();
    }

    // ---- bounce through smem for coalesced epilogue (stride 130 floats) ----
    float* Ct = (float*)smem;
#pragma unroll
    for (int mt = 0; mt < 2; mt++) {
        int row = mw + 16 * mt + (lid >> 2);
        int col = nw + (lid & 3) * 2;
#pragma unroll
        for (int nt = 0; nt < NT8; nt++) {
            *(float2*)(Ct + (size_t)row * 130 + col + 8 * nt) =
                make_float2(acc[mt][nt][0], acc[mt][nt][1]);
            *(float2*)(Ct + (size_t)(row + 8) * 130 + col + 8 * nt) =
                make_float2(acc[mt][nt][2], acc[mt][nt][3]);
        }
    }
    __syncthreads();

    // ---- epilogue: coalesced float2 writes ----
    const int tn = (tid & 63) * 2;
    const int ms = tid >> 6;  // 0..3
#pragma unroll 4
    for (int m = ms; m < MT; m += 4) {
        float2 v = *(float2*)(Ct + (size_t)m * 130 + tn);
        if constexpr (MODE == M_SIM) {
            float dq = g_dotQ[b * Q_ + m0 + m];
            float2 dd = *(const float2*)(g_dotD + b * D_ + n0 + tn);
            *(float2*)(g_sim + (size_t)b * Q_ * D_ + (size_t)(m0 + m) * D_ + n0 + tn) =
                make_float2(v.x + dq + dd.x, v.y + dq + dd.y);
        } else if constexpr (MODE == M_DD2Q) {
            int c = m0 + m, n = n0 + tn;
            size_t ob = (size_t)b * 4 * C_ * D_;
            float2 dv = *(const float2*)(doc + (size_t)b * C_ * D_ + (size_t)c * D_ + n);
            *(float2*)(out_d + ob + (size_t)c * D_ + n) = dv;
            *(float2*)(out_d + ob + (size_t)(C_ + c) * D_ + n) = v;
            *(float2*)(out_d + ob + (size_t)(2 * C_ + c) * D_ + n) = make_float2(dv.x * v.x, dv.y * v.y);
        } else if constexpr (MODE == M_QQ2D) {
            int c = m0 + m, n = tn;
            size_t ob = (size_t)b * 4 * C_ * Q_;
            float2 qv = *(const float2*)(query + (size_t)b * C_ * Q_ + (size_t)c * Q_ + n);
            *(float2*)(out_q + ob + (size_t)c * Q_ + n) = qv;
            *(float2*)(out_q + ob + (size_t)(C_ + c) * Q_ + n) = v;
            *(float2*)(out_q + ob + (size_t)(2 * C_ + c) * Q_ + n) = make_float2(qv.x * v.x, qv.y * v.y);
        } else if constexpr (MODE == M_DQ2D) {
            int c = m0 + m, n = n0 + tn;
            float2 dv = *(const float2*)(doc + (size_t)b * C_ * D_ + (size_t)c * D_ + n);
            *(float2*)(out_d + (size_t)b * 4 * C_ * D_ + (size_t)(3 * C_ + c) * D_ + n) =
                make_float2(dv.x * v.x, dv.y * v.y);
        } else {  // M_QD2Q
            int c = m0 + m, n = tn;
            float2 qv = *(const float2*)(query + (size_t)b * C_ * Q_ + (size_t)c * Q_ + n);
            *(float2*)(out_q + (size_t)b * 4 * C_ * Q_ + (size_t)(3 * C_ + c) * Q_ + n) =
                make_float2(qv.x * v.x, qv.y * v.y);
        }
    }
}

// ---------------- launcher (kernel launches ONLY — capture-safe) -------------
extern "C" void kernel_launch(void* const* d_in, const int* in_sizes, int n_in,
                              void* d_out, int out_size) {
    const float* doc   = (const float*)d_in[0];
    const float* query = (const float*)d_in[1];
    const float* W     = (const float*)d_in[2];
    float* out_d = (float*)d_out;
    float* out_q = out_d + (size_t)B_ * 4 * C_ * D_;

    dots_kernel<<<(B_ * D_ + B_ * Q_ + 255) / 256, 256>>>(doc, query, W);

    mma_gemm<M_SIM, 256><<<dim3(8, 2, 32), 256>>>(doc, query, W, out_d, out_q);

    softmax_q_kernel<<<dim3(D_ / 256, B_), 256>>>();
    softmax_d_kernel<<<dim3(Q_, B_), 256>>>();

    mma_gemm<M_DD2Q, 128><<<dim3(8, 4, 32), 256>>>(doc, query, W, out_d, out_q);
    mma_gemm<M_QQ2D, 1024><<<dim3(1, 4, 32), 256>>>(doc, query, W, out_d, out_q);
    mma_gemm<M_DQ2D, 128><<<dim3(8, 4, 32), 256>>>(doc, query, W, out_d, out_q);
    mma_gemm<M_QD2Q, 1024><<<dim3(1, 4, 32), 256>>>(doc, query, W, out_d, out_q);
}